// round 1
// baseline (speedup 1.0000x reference)
#include <cuda_runtime.h>
#include <math.h>

#define HW 16384      // 128*128
#define NB 8          // batch
#define NIC 128       // input channels (both convs)

// Scratch (device globals; allocation inside kernel_launch is forbidden)
__device__ float g_qkv1[50331648];   // [8][384][16384]  conv1x1 output
__device__ float g_qkv2[50331648];   // [8][384][16384]  dwconv output
__device__ float g_aout[16777216];   // [8][128][16384]  attention output

// ---------------------------------------------------------------------------
// conv1x1: y[b][oc][s] = sum_ic w[oc][ic] * x[b][ic][s] + bias[oc]
// grid: (spatial tiles=128, OC/128, B), block 256, dyn smem = 2*128*132*4
// Thread (tx,ty) in 16x16 grid computes 8x8 outputs at rows ty+16m, cols tx+16n.
// ---------------------------------------------------------------------------
__global__ void conv1x1_k(const float* __restrict__ x, const float* __restrict__ w,
                          const float* __restrict__ bias, float* __restrict__ y,
                          int OCtot) {
    extern __shared__ float sm[];
    float* ws = sm;             // [128][132]  w[oc][ic]
    float* xs = sm + 128 * 132; // [128][132]  x[ic][s]

    const int tid = threadIdx.x;
    const int tx = tid & 15, ty = tid >> 4;
    const int s0  = blockIdx.x * 128;
    const int oc0 = blockIdx.y * 128;
    const int b   = blockIdx.z;

    const float4* wg = (const float4*)(w + (size_t)oc0 * NIC);
    const float4* xg = (const float4*)(x + (size_t)b * NIC * HW + s0);

    #pragma unroll
    for (int i = 0; i < 16; i++) {
        int idx4 = tid + i * 256;      // 4096 float4 = 128x128 floats
        int row  = idx4 >> 5;          // 32 float4 per row
        int c4   = idx4 & 31;
        float4 wv = wg[row * 32 + c4];
        *(float4*)&ws[row * 132 + c4 * 4] = wv;
        float4 xv = xg[row * (HW / 4) + c4];
        *(float4*)&xs[row * 132 + c4 * 4] = xv;
    }
    __syncthreads();

    float acc[8][8];
    #pragma unroll
    for (int m = 0; m < 8; m++)
        #pragma unroll
        for (int n = 0; n < 8; n++) acc[m][n] = 0.f;

    #pragma unroll 4
    for (int ic = 0; ic < 128; ic++) {
        float a[8], bb[8];
        #pragma unroll
        for (int m = 0; m < 8; m++) a[m] = ws[(ty + 16 * m) * 132 + ic];
        #pragma unroll
        for (int n = 0; n < 8; n++) bb[n] = xs[ic * 132 + tx + 16 * n];
        #pragma unroll
        for (int m = 0; m < 8; m++)
            #pragma unroll
            for (int n = 0; n < 8; n++)
                acc[m][n] = fmaf(a[m], bb[n], acc[m][n]);
    }

    #pragma unroll
    for (int m = 0; m < 8; m++) {
        int oc = oc0 + ty + 16 * m;
        float bi = bias[oc];
        float* yr = y + ((size_t)b * OCtot + oc) * HW + s0;
        #pragma unroll
        for (int n = 0; n < 8; n++)
            yr[tx + 16 * n] = acc[m][n] + bi;
    }
}

// ---------------------------------------------------------------------------
// depthwise 3x3, pad 1. grid: (4 row-tiles, B*384), block 256.
// ---------------------------------------------------------------------------
__global__ void dw3x3_k(const float* __restrict__ in, const float* __restrict__ w,
                        const float* __restrict__ bias, float* __restrict__ out) {
    __shared__ float sm[34 * 128];
    const int tid = threadIdx.x;
    const int bc  = blockIdx.y;        // b*384 + c
    const int c   = bc % 384;
    const int h0  = blockIdx.x * 32;

    const float* src = in + (size_t)bc * HW;
    for (int idx = tid; idx < 34 * 128; idx += 256) {
        int r = idx >> 7, col = idx & 127;
        int h = h0 - 1 + r;
        sm[idx] = (h >= 0 && h < 128) ? src[h * 128 + col] : 0.f;
    }
    float wv[9];
    #pragma unroll
    for (int i = 0; i < 9; i++) wv[i] = w[c * 9 + i];
    const float bi = bias[c];
    __syncthreads();

    float* dst = out + (size_t)bc * HW + h0 * 128;
    for (int idx = tid; idx < 32 * 128; idx += 256) {
        int r = idx >> 7, col = idx & 127;
        float acc = bi;
        #pragma unroll
        for (int dy = 0; dy < 3; dy++) {
            #pragma unroll
            for (int dx = 0; dx < 3; dx++) {
                int cc = col + dx - 1;
                float v = (cc >= 0 && cc < 128) ? sm[(r + dy) * 128 + cc] : 0.f;
                acc = fmaf(wv[dy * 3 + dx], v, acc);
            }
        }
        dst[idx] = acc;
    }
}

// ---------------------------------------------------------------------------
// Per-(b,head,c) attention. One CTA per slice (1024 CTAs), block 256.
//   qt[w][h] = q (transposed), kt[w][h] = k (transposed), vs[h][w] = v
//   attn[j][k] = softmax_j( (q_colj . k_colk) * rnq[j]*rnk[k] * temp )
//   out[i][k]  = sum_j v[i][j] * attn[j][k]
// smem pad 133 (gcd(133 mod 32 =5, 32)=1) -> conflict-free everywhere.
// dyn smem = 3*128*133*4 = 204288
// ---------------------------------------------------------------------------
__global__ void attn_k(const float* __restrict__ qkv, const float* __restrict__ temp,
                       float* __restrict__ out) {
    extern __shared__ float sm[];
    float* qt = sm;                 // [128][133]; reused as attn buffer
    float* kt = sm + 128 * 133;
    float* vs = sm + 2 * 128 * 133;
    __shared__ float rnq[128], rnk[128];

    const int tid = threadIdx.x;
    const int tx = tid & 15, ty = tid >> 4;
    const int cid = blockIdx.x;
    const int qc  = cid & 127;      // head*32 + c
    const int b   = cid >> 7;
    const int hd  = qc >> 5;        // head index

    const float* qg = qkv + ((size_t)b * 384 + qc) * HW;
    const float* kg = qg + 128 * HW;
    const float* vg = qg + 256 * HW;

    for (int idx = tid; idx < HW; idx += 256) {
        int h = idx >> 7, w = idx & 127;
        qt[w * 133 + h] = qg[idx];
        kt[w * 133 + h] = kg[idx];
        vs[h * 133 + w] = vg[idx];
    }
    __syncthreads();

    // Column L2 norms (q: threads 0..127, k: threads 128..255)
    if (tid < 128) {
        float s = 0.f;
        #pragma unroll 4
        for (int i = 0; i < 128; i++) { float v = qt[tid * 133 + i]; s = fmaf(v, v, s); }
        rnq[tid] = 1.f / fmaxf(sqrtf(s), 1e-12f);
    } else {
        int j = tid - 128;
        float s = 0.f;
        #pragma unroll 4
        for (int i = 0; i < 128; i++) { float v = kt[j * 133 + i]; s = fmaf(v, v, s); }
        rnk[j] = 1.f / fmaxf(sqrtf(s), 1e-12f);
    }

    // GEMM1: acc[j][k] = sum_i qt[j][i]*kt[k][i]
    float acc[8][8];
    #pragma unroll
    for (int m = 0; m < 8; m++)
        #pragma unroll
        for (int n = 0; n < 8; n++) acc[m][n] = 0.f;

    #pragma unroll 4
    for (int i = 0; i < 128; i++) {
        float a[8], bb[8];
        #pragma unroll
        for (int m = 0; m < 8; m++) a[m] = qt[(ty + 16 * m) * 133 + i];
        #pragma unroll
        for (int n = 0; n < 8; n++) bb[n] = kt[(tx + 16 * n) * 133 + i];
        #pragma unroll
        for (int m = 0; m < 8; m++)
            #pragma unroll
            for (int n = 0; n < 8; n++)
                acc[m][n] = fmaf(a[m], bb[n], acc[m][n]);
    }
    const float tp = temp[hd];
    __syncthreads();   // all qt reads done; rnq/rnk ready

    // Write scaled attn logits into qt buffer
    #pragma unroll
    for (int m = 0; m < 8; m++) {
        int j = ty + 16 * m;
        float rq = rnq[j] * tp;
        #pragma unroll
        for (int n = 0; n < 8; n++) {
            int k = tx + 16 * n;
            qt[j * 133 + k] = acc[m][n] * rq * rnk[k];
        }
    }
    __syncthreads();

    // Softmax over j for each column k (threads 0..127)
    if (tid < 128) {
        int k = tid;
        float mx = -1e30f;
        for (int j = 0; j < 128; j++) mx = fmaxf(mx, qt[j * 133 + k]);
        float s = 0.f;
        for (int j = 0; j < 128; j++) {
            float e = expf(qt[j * 133 + k] - mx);
            qt[j * 133 + k] = e;
            s += e;
        }
        float inv = 1.f / s;
        for (int j = 0; j < 128; j++) qt[j * 133 + k] *= inv;
    }
    __syncthreads();

    // GEMM2: o[i][k] = sum_j vs[i][j] * attn[j][k]
    float o[8][8];
    #pragma unroll
    for (int m = 0; m < 8; m++)
        #pragma unroll
        for (int n = 0; n < 8; n++) o[m][n] = 0.f;

    #pragma unroll 4
    for (int j = 0; j < 128; j++) {
        float a[8], bb[8];
        #pragma unroll
        for (int m = 0; m < 8; m++) a[m] = vs[(ty + 16 * m) * 133 + j];
        #pragma unroll
        for (int n = 0; n < 8; n++) bb[n] = qt[j * 133 + tx + 16 * n];
        #pragma unroll
        for (int m = 0; m < 8; m++)
            #pragma unroll
            for (int n = 0; n < 8; n++)
                o[m][n] = fmaf(a[m], bb[n], o[m][n]);
    }

    float* og = out + ((size_t)b * 128 + qc) * HW;
    #pragma unroll
    for (int m = 0; m < 8; m++) {
        int i = ty + 16 * m;
        #pragma unroll
        for (int n = 0; n < 8; n++)
            og[i * 128 + tx + 16 * n] = o[m][n];
    }
}

// ---------------------------------------------------------------------------
extern "C" void kernel_launch(void* const* d_in, const int* in_sizes, int n_in,
                              void* d_out, int out_size) {
    const float* x      = (const float*)d_in[0];
    const float* qkv_w  = (const float*)d_in[1];
    const float* qkv_b  = (const float*)d_in[2];
    const float* dw_w   = (const float*)d_in[3];
    const float* dw_b   = (const float*)d_in[4];
    const float* proj_w = (const float*)d_in[5];
    const float* proj_b = (const float*)d_in[6];
    const float* temp   = (const float*)d_in[7];
    float* out = (float*)d_out;

    void *p1, *p2, *p3;
    cudaGetSymbolAddress(&p1, g_qkv1);
    cudaGetSymbolAddress(&p2, g_qkv2);
    cudaGetSymbolAddress(&p3, g_aout);
    float* qkv1 = (float*)p1;
    float* qkv2 = (float*)p2;
    float* aout = (float*)p3;

    const int conv_smem = 2 * 128 * 132 * 4;   // 135168
    const int attn_smem = 3 * 128 * 133 * 4;   // 204288
    cudaFuncSetAttribute(conv1x1_k, cudaFuncAttributeMaxDynamicSharedMemorySize, conv_smem);
    cudaFuncSetAttribute(attn_k,    cudaFuncAttributeMaxDynamicSharedMemorySize, attn_smem);

    // 1) qkv = conv1x1(x)
    conv1x1_k<<<dim3(128, 3, NB), 256, conv_smem>>>(x, qkv_w, qkv_b, qkv1, 384);
    // 2) qkv = dwconv3x3(qkv)
    dw3x3_k<<<dim3(4, NB * 384), 256>>>(qkv1, dw_w, dw_b, qkv2);
    // 3) transposed attention per (b, head, c)
    attn_k<<<dim3(1024), 256, attn_smem>>>(qkv2, temp, aout);
    // 4) out = conv1x1(attn_out)
    conv1x1_k<<<dim3(128, 1, NB), 256, conv_smem>>>(aout, proj_w, proj_b, out, 128);
}

// round 3
// speedup vs baseline: 1.1820x; 1.1820x over previous
#include <cuda_runtime.h>
#include <math.h>

#define HW 16384      // 128*128
#define NB 8          // batch

typedef unsigned long long u64;

__device__ __forceinline__ u64 pk2(float x) {
    u64 r; asm("mov.b64 %0,{%1,%1};" : "=l"(r) : "f"(x)); return r;
}
__device__ __forceinline__ u64 pk2b(float x, float y) {
    u64 r; asm("mov.b64 %0,{%1,%2};" : "=l"(r) : "f"(x), "f"(y)); return r;
}
__device__ __forceinline__ void up2(u64 v, float& x, float& y) {
    asm("mov.b64 {%0,%1},%2;" : "=f"(x), "=f"(y) : "l"(v));
}
__device__ __forceinline__ u64 fma2(u64 a, u64 b, u64 c) {
    u64 d; asm("fma.rn.f32x2 %0,%1,%2,%3;" : "=l"(d) : "l"(a), "l"(b), "l"(c)); return d;
}
__device__ __forceinline__ u64 mul2(u64 a, u64 b) {
    u64 d; asm("mul.rn.f32x2 %0,%1,%2;" : "=l"(d) : "l"(a), "l"(b)); return d;
}

// Scratch (device globals; allocation inside kernel_launch is forbidden)
__device__ float g_qkv1[50331648];   // [8][384][16384]  conv1x1 output
__device__ float g_qkv2[50331648];   // [8][384][16384]  dwconv output
__device__ float g_aout[16777216];   // [8][128][16384]  attention output

// ---------------------------------------------------------------------------
// conv1x1: y[b][oc][s] = sum_ic w[oc][ic] * x[b][ic][s] + bias[oc]
// grid: (128 spatial tiles, OC/128, B), block 512, dyn smem = 2*128*132*4
// Thread (tx in [0,16), ty in [0,32)): rows ty+32m (m<4), cols 2*tx+32n (n<4, f32x2).
// ---------------------------------------------------------------------------
__global__ void __launch_bounds__(512, 1)
conv1x1_k(const float* __restrict__ x, const float* __restrict__ w,
          const float* __restrict__ bias, float* __restrict__ y, int OCtot) {
    extern __shared__ float sm[];
    float* ws = sm;             // [128][132]
    float* xs = sm + 128 * 132; // [128][132]

    const int tid = threadIdx.x;
    const int tx = tid & 15, ty = tid >> 4;
    const int s0  = blockIdx.x * 128;
    const int oc0 = blockIdx.y * 128;
    const int b   = blockIdx.z;

    const float4* wg = (const float4*)(w + (size_t)oc0 * 128);
    const float4* xg = (const float4*)(x + (size_t)b * 128 * HW + s0);

    #pragma unroll
    for (int i = 0; i < 8; i++) {
        int idx4 = tid + i * 512;       // 4096 float4 = 128x128 floats
        int row  = idx4 >> 5, c4 = idx4 & 31;
        *(float4*)&ws[row * 132 + c4 * 4] = wg[row * 32 + c4];
        *(float4*)&xs[row * 132 + c4 * 4] = xg[row * (HW / 4) + c4];
    }
    __syncthreads();

    u64 acc[4][4];
    #pragma unroll
    for (int m = 0; m < 4; m++)
        #pragma unroll
        for (int n = 0; n < 4; n++) acc[m][n] = 0ULL;

    #pragma unroll 4
    for (int ic = 0; ic < 128; ic++) {
        u64 a[4], bv[4];
        #pragma unroll
        for (int m = 0; m < 4; m++) a[m] = pk2(ws[(ty + 32 * m) * 132 + ic]);
        #pragma unroll
        for (int n = 0; n < 4; n++) bv[n] = *(const u64*)&xs[ic * 132 + 2 * tx + 32 * n];
        #pragma unroll
        for (int m = 0; m < 4; m++)
            #pragma unroll
            for (int n = 0; n < 4; n++)
                acc[m][n] = fma2(a[m], bv[n], acc[m][n]);
    }

    #pragma unroll
    for (int m = 0; m < 4; m++) {
        int oc = oc0 + ty + 32 * m;
        float bi = bias[oc];
        float* yr = y + ((size_t)b * OCtot + oc) * HW + s0;
        #pragma unroll
        for (int n = 0; n < 4; n++) {
            float lo, hi; up2(acc[m][n], lo, hi);
            float2 o; o.x = lo + bi; o.y = hi + bi;
            *(float2*)&yr[2 * tx + 32 * n] = o;
        }
    }
}

// ---------------------------------------------------------------------------
// depthwise 3x3, pad 1. grid: (4 row-tiles, B*384), block 256.
// ---------------------------------------------------------------------------
__global__ void dw3x3_k(const float* __restrict__ in, const float* __restrict__ w,
                        const float* __restrict__ bias, float* __restrict__ out) {
    __shared__ float sm[34 * 128];
    const int tid = threadIdx.x;
    const int bc  = blockIdx.y;        // b*384 + c
    const int c   = bc % 384;
    const int h0  = blockIdx.x * 32;

    const float* src = in + (size_t)bc * HW;
    for (int idx = tid; idx < 34 * 128; idx += 256) {
        int r = idx >> 7, col = idx & 127;
        int h = h0 - 1 + r;
        sm[idx] = (h >= 0 && h < 128) ? src[h * 128 + col] : 0.f;
    }
    float wv[9];
    #pragma unroll
    for (int i = 0; i < 9; i++) wv[i] = w[c * 9 + i];
    const float bi = bias[c];
    __syncthreads();

    float* dst = out + (size_t)bc * HW + h0 * 128;
    for (int idx = tid; idx < 32 * 128; idx += 256) {
        int r = idx >> 7, col = idx & 127;
        float acc = bi;
        #pragma unroll
        for (int dy = 0; dy < 3; dy++) {
            #pragma unroll
            for (int dx = 0; dx < 3; dx++) {
                int cc = col + dx - 1;
                float v = (cc >= 0 && cc < 128) ? sm[(r + dy) * 128 + cc] : 0.f;
                acc = fmaf(wv[dy * 3 + dx], v, acc);
            }
        }
        dst[idx] = acc;
    }
}

// ---------------------------------------------------------------------------
// Per-(b,head,c) attention. One CTA per slice (1024 CTAs), block 512.
// All tiles stay ROW-MAJOR (no transposes):
//   GEMM1: logits[j][k] = sum_i qs[i][j]*ks[i][k]   (contraction over rows)
//   scaled by rnq[j]*rnk[k]*temp, written into qs (reused)
//   softmax over j (columns), 1/sum folded into GEMM2 epilogue
//   GEMM2: out[i][k] = sum_j vs[i][j]*attn[j][k]
// dyn smem = 3*128*132*4 = 202752
// ---------------------------------------------------------------------------
__global__ void __launch_bounds__(512, 1)
attn_k(const float* __restrict__ qkv, const float* __restrict__ temp,
       float* __restrict__ out) {
    extern __shared__ float sm[];
    float* qs = sm;                 // [128][132]; reused as attn buffer
    float* ks = sm + 128 * 132;
    float* vs = sm + 2 * 128 * 132;
    __shared__ float rnq[128], rnk[128], sinv[128], psum[4 * 128];

    const int tid = threadIdx.x;
    const int tx = tid & 15, ty = tid >> 4;
    const int cid = blockIdx.x;
    const int qc  = cid & 127;      // head*32 + c
    const int b   = cid >> 7;
    const int hd  = qc >> 5;        // head index

    const float4* qg = (const float4*)(qkv + ((size_t)b * 384 + qc) * HW);
    const float4* kg = (const float4*)(qkv + ((size_t)b * 384 + qc + 128) * HW);
    const float4* vg = (const float4*)(qkv + ((size_t)b * 384 + qc + 256) * HW);

    #pragma unroll
    for (int i = 0; i < 8; i++) {
        int idx4 = tid + i * 512;
        int row = idx4 >> 5, c4 = idx4 & 31;
        int d = row * 132 + c4 * 4;
        *(float4*)&qs[d] = qg[idx4];
        *(float4*)&ks[d] = kg[idx4];
        *(float4*)&vs[d] = vg[idx4];
    }
    __syncthreads();

    // Column L2 norms along H (rows): q by threads 0..127, k by 128..255
    if (tid < 128) {
        float s = 0.f;
        #pragma unroll 8
        for (int i = 0; i < 128; i++) { float v = qs[i * 132 + tid]; s = fmaf(v, v, s); }
        rnq[tid] = 1.f / fmaxf(sqrtf(s), 1e-12f);
    } else if (tid < 256) {
        int j = tid - 128;
        float s = 0.f;
        #pragma unroll 8
        for (int i = 0; i < 128; i++) { float v = ks[i * 132 + j]; s = fmaf(v, v, s); }
        rnk[j] = 1.f / fmaxf(sqrtf(s), 1e-12f);
    }

    // GEMM1: acc[j][k] = sum_i qs[i][j]*ks[i][k]
    u64 acc[4][4];
    #pragma unroll
    for (int m = 0; m < 4; m++)
        #pragma unroll
        for (int n = 0; n < 4; n++) acc[m][n] = 0ULL;

    #pragma unroll 4
    for (int i = 0; i < 128; i++) {
        u64 a[4], bv[4];
        #pragma unroll
        for (int m = 0; m < 4; m++) a[m] = pk2(qs[i * 132 + ty + 32 * m]);
        #pragma unroll
        for (int n = 0; n < 4; n++) bv[n] = *(const u64*)&ks[i * 132 + 2 * tx + 32 * n];
        #pragma unroll
        for (int m = 0; m < 4; m++)
            #pragma unroll
            for (int n = 0; n < 4; n++)
                acc[m][n] = fma2(a[m], bv[n], acc[m][n]);
    }
    const float tp = temp[hd];
    __syncthreads();   // GEMM1 reads of qs done; rnq/rnk ready

    // Write scaled logits into qs (row j, col k)
    #pragma unroll
    for (int m = 0; m < 4; m++) {
        int j = ty + 32 * m;
        float rq = rnq[j] * tp;
        #pragma unroll
        for (int n = 0; n < 4; n++) {
            int k0 = 2 * tx + 32 * n;
            u64 sc = pk2b(rnk[k0] * rq, rnk[k0 + 1] * rq);
            *(u64*)&qs[j * 132 + k0] = mul2(acc[m][n], sc);
        }
    }
    __syncthreads();

    // Softmax over j per column k. Logits are bounded by |temp| (cosine sims),
    // so no max subtraction needed. 4 segments of 32 rows per column.
    {
        int col = tid & 127, seg = tid >> 7;
        int r0 = seg * 32;
        float s = 0.f;
        #pragma unroll 8
        for (int r = 0; r < 32; r++) {
            int o = (r0 + r) * 132 + col;
            float e = __expf(qs[o]);
            qs[o] = e;
            s += e;
        }
        psum[seg * 128 + col] = s;
    }
    __syncthreads();
    if (tid < 128)
        sinv[tid] = 1.f / (psum[tid] + psum[128 + tid] + psum[256 + tid] + psum[384 + tid]);
    __syncthreads();

    // GEMM2: o[i][k] = sum_j vs[i][j] * exp[j][k], scaled by sinv[k] at the end
    u64 oacc[4][4];
    #pragma unroll
    for (int m = 0; m < 4; m++)
        #pragma unroll
        for (int n = 0; n < 4; n++) oacc[m][n] = 0ULL;

    #pragma unroll 4
    for (int j = 0; j < 128; j++) {
        u64 a[4], bv[4];
        #pragma unroll
        for (int m = 0; m < 4; m++) a[m] = pk2(vs[(ty + 32 * m) * 132 + j]);
        #pragma unroll
        for (int n = 0; n < 4; n++) bv[n] = *(const u64*)&qs[j * 132 + 2 * tx + 32 * n];
        #pragma unroll
        for (int m = 0; m < 4; m++)
            #pragma unroll
            for (int n = 0; n < 4; n++)
                oacc[m][n] = fma2(a[m], bv[n], oacc[m][n]);
    }

    float* og = out + ((size_t)b * 128 + qc) * HW;
    #pragma unroll
    for (int m = 0; m < 4; m++) {
        int i = ty + 32 * m;
        #pragma unroll
        for (int n = 0; n < 4; n++) {
            int k0 = 2 * tx + 32 * n;
            float lo, hi; up2(oacc[m][n], lo, hi);
            float2 o; o.x = lo * sinv[k0]; o.y = hi * sinv[k0 + 1];
            *(float2*)&og[i * 128 + k0] = o;
        }
    }
}

// ---------------------------------------------------------------------------
extern "C" void kernel_launch(void* const* d_in, const int* in_sizes, int n_in,
                              void* d_out, int out_size) {
    const float* x      = (const float*)d_in[0];
    const float* qkv_w  = (const float*)d_in[1];
    const float* qkv_b  = (const float*)d_in[2];
    const float* dw_w   = (const float*)d_in[3];
    const float* dw_b   = (const float*)d_in[4];
    const float* proj_w = (const float*)d_in[5];
    const float* proj_b = (const float*)d_in[6];
    const float* temp   = (const float*)d_in[7];
    float* out = (float*)d_out;

    void *p1, *p2, *p3;
    cudaGetSymbolAddress(&p1, g_qkv1);
    cudaGetSymbolAddress(&p2, g_qkv2);
    cudaGetSymbolAddress(&p3, g_aout);
    float* qkv1 = (float*)p1;
    float* qkv2 = (float*)p2;
    float* aout = (float*)p3;

    const int conv_smem = 2 * 128 * 132 * 4;   // 135168
    const int attn_smem = 3 * 128 * 132 * 4;   // 202752
    cudaFuncSetAttribute(conv1x1_k, cudaFuncAttributeMaxDynamicSharedMemorySize, conv_smem);
    cudaFuncSetAttribute(attn_k,    cudaFuncAttributeMaxDynamicSharedMemorySize, attn_smem);

    // 1) qkv = conv1x1(x)
    conv1x1_k<<<dim3(128, 3, NB), 512, conv_smem>>>(x, qkv_w, qkv_b, qkv1, 384);
    // 2) qkv = dwconv3x3(qkv)
    dw3x3_k<<<dim3(4, NB * 384), 256>>>(qkv1, dw_w, dw_b, qkv2);
    // 3) transposed attention per (b, head, c)
    attn_k<<<dim3(1024), 512, attn_smem>>>(qkv2, temp, aout);
    // 4) out = conv1x1(attn_out)
    conv1x1_k<<<dim3(128, 1, NB), 512, conv_smem>>>(aout, proj_w, proj_b, out, 128);
}